// round 1
// baseline (speedup 1.0000x reference)
#include <cuda_runtime.h>

// SphericalBessel: Miller downward recurrence, double-single (compensated fp32)
// precision to reproduce the float64 reference's trajectory (including the
// near-singular normalization outliers) to ~1e-13 relative per step.
//
// Output [N, L, K] fp32. Thread = one (n,k). Warp = one n, k=0..31 -> coalesced
// 128B stores per l, broadcast load of r[n].

#define NPTS   65536
#define KMAX   32
#define LMAX   32
#define LSTART 49   // L_MAX + int(sqrt(10*L_MAX)) = 32 + 17

__global__ void __launch_bounds__(256)
sph_bessel_kernel(const float* __restrict__ r, float* __restrict__ out) {
    int tid = blockIdx.x * 256 + threadIdx.x;
    int n  = tid >> 5;
    int kk = tid & 31;               // 0..31  (k = kk+1)
    float kf = (float)(kk + 1);
    float rv = __ldg(&r[n]);

    // x = r*k kept EXACT as a double-single pair (fp32 rounding of x would
    // perturb the oscillation phase by ~2e-5*A -> fails on outlier elements).
    float xh = rv * kf;
    float xl = fmaf(rv, kf, -xh);    // exact residual (24b * 6b fits in 2 fp32)

    // DS reciprocal of x: one Newton correction off the true residual gives
    // ~1e-14 relative regardless of initial div rounding.
    float ih = 1.0f / xh;
    float tr = fmaf(xh, ih, -1.0f);
    tr = fmaf(xl, ih, tr);
    float il = -ih * tr;

    // recurrence state (double-single)
    float j1h = 1.0f, j1l = 0.0f;    // init (j1, j2) = (1, 0)
    float j2h = 0.0f, j2l = 0.0f;
    float y[LMAX];

    const float THR = 0x1p100f;      // rescale threshold
    const float SCL = 0x1p-100f;     // exact power-of-two scale (no rounding)

    #pragma unroll
    for (int i = LSTART; i >= 1; --i) {
        float c = (float)(2 * i + 1);        // exact small integer

        // a = c * inv   (DS)
        float ah = c * ih;
        float ae = fmaf(c, ih, -ah);
        float al = fmaf(c, il, ae);

        // t = a * j1    (DS product: hi + compensated error term)
        float th = ah * j1h;
        float te = fmaf(ah, j1h, -th);
        te = fmaf(ah, j1l, te);
        te = fmaf(al, j1h, te);

        // s = t - j2    (branchless Knuth two-sum with b = -j2h)
        float sh  = th - j2h;
        float v   = sh - th;
        float err = (th - (sh - v)) - (j2h + v);
        float lo  = err + te - j2l;

        // renormalize (order-free two-sum: sh may be tiny under cancellation)
        float j0h = sh + lo;
        float v2  = j0h - sh;
        float j0l = (sh - (j0h - v2)) + (lo - v2);

        // advance carry
        j2h = j1h; j2l = j1l;
        j1h = j0h; j1l = j0l;

        // Rescale (rare: <= ~4 times/thread, only for small x). Exact *2^-100
        // applied to the carry AND all already-stored y -> one consistent scale.
        if (fabsf(j1h) > THR) {
            j1h *= SCL; j1l *= SCL; j2h *= SCL; j2l *= SCL;
            #pragma unroll
            for (int m = i; m < LMAX; ++m) y[m] *= SCL;
        }

        if (i <= LMAX) y[i - 1] = j1h;   // y[l] = j0 at step i = l+1
    }

    // Normalization: true j0 = sin(x)/x, with x_lo phase compensation
    // (sin(xh + xl) ~ sin(xh) + xl*cos(xh)).
    float s, cc;
    sincosf(xh, &s, &cc);
    s = fmaf(xl, cc, s);
    float truej0 = s / xh;
    float norm = truej0 / y[0] * 0.7978845608028654f * kf;  // sqrt(2/pi)*k

    float* o = out + (size_t)n * (LMAX * KMAX) + kk;
    #pragma unroll
    for (int l = 0; l < LMAX; ++l)
        o[(size_t)l * KMAX] = y[l] * norm;   // warp-coalesced 128B per l
}

extern "C" void kernel_launch(void* const* d_in, const int* in_sizes, int n_in,
                              void* d_out, int out_size) {
    const float* r = (const float*)d_in[0];
    float* out = (float*)d_out;
    int total = NPTS * KMAX;               // 2,097,152 threads
    sph_bessel_kernel<<<total / 256, 256>>>(r, out);
}

// round 2
// speedup vs baseline: 1.0468x; 1.0468x over previous
#include <cuda_runtime.h>

// SphericalBessel via Miller downward recurrence, double-single (compensated
// fp32) arithmetic, PACKED two-k-per-thread using sm_103a f32x2 ops (FFMA2).
//
// Sign-alternating reformulation: step t computes C = (±a)*A + B (pure
// additive two-sum, signs compile-time, period 4), so no runtime negations.
// All subtractions are fma(b, NEG1, a). Exact negated products come from
// multiplying by the negated compile-time constant.
//
// Thread = one n, two adjacent k (2p+1, 2p+2). Warp = 2 n x 16 pairs.
// Stores: float2 per l -> 128B coalesced per half-warp.

#define NPTS   65536
#define KMAX   32
#define LMAX   32
#define LSTART 49   // L_MAX + int(sqrt(10*L_MAX)) = 32 + 17

typedef unsigned long long u64;

__device__ __forceinline__ u64 pk(float lo, float hi) {
    u64 r; asm("mov.b64 %0,{%1,%2};" : "=l"(r) : "f"(lo), "f"(hi)); return r;
}
__device__ __forceinline__ void upk(u64 v, float& lo, float& hi) {
    asm("mov.b64 {%0,%1},%2;" : "=f"(lo), "=f"(hi) : "l"(v));
}
__device__ __forceinline__ u64 f2mul(u64 a, u64 b) {
    u64 d; asm("mul.rn.f32x2 %0,%1,%2;" : "=l"(d) : "l"(a), "l"(b)); return d;
}
__device__ __forceinline__ u64 f2add(u64 a, u64 b) {
    u64 d; asm("add.rn.f32x2 %0,%1,%2;" : "=l"(d) : "l"(a), "l"(b)); return d;
}
__device__ __forceinline__ u64 f2fma(u64 a, u64 b, u64 c) {
    u64 d; asm("fma.rn.f32x2 %0,%1,%2,%3;" : "=l"(d) : "l"(a), "l"(b), "l"(c)); return d;
}
#define NEG1P 0xBF800000BF800000ULL             /* (-1.0f, -1.0f) */
__device__ __forceinline__ u64 f2sub(u64 a, u64 b) { return f2fma(b, NEG1P, a); }

__global__ void __launch_bounds__(256)
sph_bessel_pk(const float* __restrict__ r, float* __restrict__ out) {
    int tid = blockIdx.x * 256 + threadIdx.x;
    int n  = tid >> 4;          // two n per warp (lanes 0-15 / 16-31)
    int pr = tid & 15;          // k-pair index: k = 2pr+1, 2pr+2
    float k0 = (float)(2 * pr + 1);
    float k1 = (float)(2 * pr + 2);
    float rv = __ldg(&r[n]);

    // ---- prologue (scalar per half): exact DS x = r*k, DS 1/x ----
    float xh0 = rv * k0, xl0 = fmaf(rv, k0, -xh0);
    float xh1 = rv * k1, xl1 = fmaf(rv, k1, -xh1);
    float ih0 = 1.0f / xh0;
    float tr0 = fmaf(xh0, ih0, -1.0f); tr0 = fmaf(xl0, ih0, tr0);
    float il0 = -ih0 * tr0;
    float ih1 = 1.0f / xh1;
    float tr1 = fmaf(xh1, ih1, -1.0f); tr1 = fmaf(xl1, ih1, tr1);
    float il1 = -ih1 * tr1;

    u64 IH = pk(ih0, ih1), IL = pk(il0, il1);

    // state: A = signed J1 (DS), B = signed J2 (DS); init (1, 0)
    u64 Ah = pk(1.0f, 1.0f), Al = 0ull, Bh = 0ull, Bl = 0ull;
    u64 y[LMAX];

    const u64 SCLP = 0x0D8000000D800000ULL;   // (2^-100, 2^-100) exact
    const float THRf = 0x1p100f;

    #pragma unroll
    for (int i = LSTART; i >= 1; --i) {
        const int t = LSTART - i;
        const float c  = (float)(2 * i + 1);
        const float cs = (t & 1) ? c : -c;        // compile-time sign schedule
        const u64 CP  = pk(cs, cs);
        const u64 NCP = pk(-cs, -cs);

        // b = cs * inv  (DS; nbh = -bh exactly via negated constant)
        u64 bh  = f2mul(CP, IH);
        u64 nbh = f2mul(NCP, IH);
        u64 be  = f2fma(CP, IH, nbh);             // exact residual
        u64 bl  = f2fma(CP, IL, be);

        // t = b (x) A   (DS product with exact -th)
        u64 th  = f2mul(bh, Ah);
        u64 nth = f2mul(nbh, Ah);                 // = -th exactly
        u64 te  = f2fma(bh, Ah, nth);             // exact residual
        te = f2fma(bh, Al, te);
        te = f2fma(bl, Ah, te);

        // C = t (+) B   (Knuth two-sum, additive)
        u64 sh = f2add(th, Bh);
        u64 v  = f2add(sh, nth);                  // sh - th
        u64 w  = f2sub(sh, v);
        u64 e1 = f2sub(th, w);
        u64 e2 = f2sub(Bh, v);
        u64 er = f2add(e1, e2);
        u64 lo = f2add(er, te);
        lo = f2add(lo, Bl);

        // renormalize (order-free two-sum)
        u64 Ch = f2add(sh, lo);
        u64 v2 = f2sub(Ch, sh);
        u64 p1 = f2sub(Ch, v2);
        u64 p2 = f2sub(sh, p1);
        u64 p3 = f2sub(lo, v2);
        u64 Cl = f2add(p2, p3);

        Bh = Ah; Bl = Al; Ah = Ch; Al = Cl;

        if (i <= LMAX) y[i - 1] = Ah;             // register rename, free

        // overflow rescale: every 2nd step suffices (growth <= 2^20 between
        // checks, THR=2^100 -> |val| <= 2^120). Joint scale of both halves
        // is safe (halves differ by <= 2^49; deep-underflow y correspond to
        // outputs that underflow in fp32 anyway).
        if (t & 1) {
            float h0, h1; upk(Ah, h0, h1);
            if (fabsf(h0) > THRf || fabsf(h1) > THRf) {
                Ah = f2mul(Ah, SCLP); Al = f2mul(Al, SCLP);
                Bh = f2mul(Bh, SCLP); Bl = f2mul(Bl, SCLP);
                #pragma unroll
                for (int m = (i <= LMAX ? i - 1 : LMAX); m < LMAX; ++m)
                    y[m] = f2mul(y[m], SCLP);
            }
        }
    }

    // ---- normalization: true j0 = sin(x)/x with x_lo phase compensation ----
    float y00, y01; upk(y[0], y00, y01);
    float s0, c0, s1, c1;
    sincosf(xh0, &s0, &c0); s0 = fmaf(xl0, c0, s0);
    sincosf(xh1, &s1, &c1); s1 = fmaf(xl1, c1, s1);
    float nm0 = (s0 / xh0) / y00 * 0.7978845608028654f * k0;
    float nm1 = (s1 / xh1) / y01 * 0.7978845608028654f * k1;
    u64 NP = pk(nm0, nm1);
    u64 NN = pk(-nm0, -nm1);

    // stored sign schedule: l%4 in {0,3} -> +norm, {1,2} -> -norm
    float2* o = (float2*)out + (size_t)n * (LMAX * KMAX / 2) + pr;
    #pragma unroll
    for (int l = 0; l < LMAX; ++l) {
        int m = l & 3;
        u64 vv = f2mul(y[l], (m == 0 || m == 3) ? NP : NN);
        float a, b; upk(vv, a, b);
        o[(size_t)l * (KMAX / 2)] = make_float2(a, b);   // coalesced STG.64
    }
}

extern "C" void kernel_launch(void* const* d_in, const int* in_sizes, int n_in,
                              void* d_out, int out_size) {
    const float* r = (const float*)d_in[0];
    float* out = (float*)d_out;
    int total = NPTS * KMAX / 2;                 // 1,048,576 threads
    sph_bessel_pk<<<total / 256, 256>>>(r, out);
}

// round 4
// speedup vs baseline: 1.2389x; 1.1835x over previous
#include <cuda_runtime.h>

// SphericalBessel, Miller downward recurrence in the scaled variable
//   S_l = j_l * (x*sigma)^(-l),  sigma = exact per-thread power of two
// giving the branch-free recurrence  S_{l-1} = (2l+1)*sigma*S_l - (x*sigma)^2*S_{l+1}
// with (2l+1)*sigma an exact constant and X2 = (x*sigma)^2 a per-thread DS
// constant. Double-single (unnormalized pair) arithmetic; two-sum adds/subs
// emitted as FFMA with +-1.0 immediate (rt_SMSP=1 encoding).
//
// Output: out[l] = (S_l/S_0) * z^l * truej0 * sqrt(2/pi) * k,  z = x*sigma
// (z is EXACT as a DS pair since sigma is pow2; z^l folded into norm with a
//  compensated 2-FMA update per l).
//
// Thread = one (n,k). Warp = one n, k=0..31 -> coalesced 128B stores per l.

#define NPTS   65536
#define KMAX   32
#define LMAX   32
#define LSTART 49   // L_MAX + int(sqrt(10*L_MAX)) = 32 + 17

// a + b and a - b as FFMA with immediate +-1.0 multiplier (exact).
__device__ __forceinline__ float fa(float a, float b) {
    float d; asm("fma.rn.f32 %0,%1,0f3F800000,%2;" : "=f"(d) : "f"(a), "f"(b)); return d;
}
__device__ __forceinline__ float fs(float a, float b) {  // a - b
    float d; asm("fma.rn.f32 %0,%1,0fBF800000,%2;" : "=f"(d) : "f"(b), "f"(a)); return d;
}

__global__ void __launch_bounds__(256)
sph_bessel_p(const float* __restrict__ r, float* __restrict__ out) {
    int tid = blockIdx.x * 256 + threadIdx.x;
    int n  = tid >> 5;
    int kk = tid & 31;                    // k = kk+1
    float kf = (float)(kk + 1);
    float rv = __ldg(&r[n]);

    // exact DS x = r*k
    float xh = rv * kf;
    float xl = fmaf(rv, kf, -xh);

    // per-thread exact power-of-two scale: sigma = 0.25 / 2^floor(log2 max(x,99))
    // -> (2l+1)*sigma <= 0.39 and x*sigma < 0.5: state only shrinks downward,
    // no overflow/underflow (init 2^70, total shrink >= 2^-117).
    float m = fmaxf(xh, 99.0f);
    float p = __int_as_float(__float_as_int(m) & 0x7f800000);
    float sigma = 0.25f / p;              // exact pow2

    // z = x*sigma (EXACT DS: pow2 multiply), X2 = z^2 as DS
    float zh = xh * sigma, zl = xl * sigma;
    float X2h = zh * zh;
    float X2l = fmaf(zh, zh, -X2h);
    X2l = fmaf(zh, 2.0f * zl, X2l);
    X2l = fmaf(zl, zl, X2l);

    // state: A = S_l, B = S_{l+1}, unnormalized DS pairs. Init (2^70, 0).
    float Ah = 0x1p70f, Al = 0.0f, Bh = 0.0f, Bl = 0.0f;
    float y[LMAX];

    #pragma unroll
    for (int i = LSTART; i >= 1; --i) {
        float cs = (float)(2 * i + 1) * sigma;   // exact (c<=99 integer * pow2)

        // t = cs (x) A   (DS product, exact residual)
        float th = cs * Ah;
        float te = fmaf(cs, Ah, -th);
        te = fmaf(cs, Al, te);

        // u = X2 (x) B
        float uh = X2h * Bh;
        float ue = fmaf(X2h, Bh, -uh);
        ue = fmaf(X2h, Bl, ue);
        ue = fmaf(X2l, Bh, ue);

        // C = t - u : branchless Knuth two-sum of (th, -uh)
        float sh = fs(th, uh);
        float v  = fs(sh, th);
        float w  = fs(sh, v);
        float e1 = fs(th, w);
        float t1 = fa(uh, v);
        float er = fs(e1, t1);        // exact two-sum error
        float lo = fa(er, te);
        lo = fs(lo, ue);

        Bh = Ah; Bl = Al;             // register rename, free
        Ah = sh; Al = lo;

        if (i <= LMAX) y[i - 1] = fa(sh, lo);   // rounded S_l for output
    }

    // normalization: true j0 = sin(x)/x with x_lo phase compensation.
    // out[l] = y[l] * norm_l,  norm_l = (truej0*sqrt(2/pi)*k / y[0]) * z^l
    float s, cc;
    sincosf(xh, &s, &cc);
    s = fmaf(xl, cc, s);
    float truej0 = s / xh;
    float norm = truej0 / y[0] * (0.7978845608028654f * kf);

    float* o = out + (size_t)n * (LMAX * KMAX) + kk;
    #pragma unroll
    for (int l = 0; l < LMAX; ++l) {
        o[(size_t)l * KMAX] = y[l] * norm;   // warp-coalesced 128B per l
        float tz = norm * zl;                 // compensated norm *= z (DS z)
        norm = fmaf(norm, zh, tz);
    }
}

extern "C" void kernel_launch(void* const* d_in, const int* in_sizes, int n_in,
                              void* d_out, int out_size) {
    const float* r = (const float*)d_in[0];
    float* out = (float*)d_out;
    int total = NPTS * KMAX;                  // 2,097,152 threads
    sph_bessel_p<<<total / 256, 256>>>(r, out);
}

// round 5
// speedup vs baseline: 1.3755x; 1.1102x over previous
#include <cuda_runtime.h>

// SphericalBessel, Miller downward recurrence in scaled variable
//   S_l = j_l * (x*sigma)^(-l),  sigma = exact per-thread power of two.
// Branch-free recurrence  S_{l-1} = (2l+1)*sigma*S_l - (x*sigma)^2*S_{l+1},
// double-single (unnormalized pair) arithmetic.
//
// Issue-trimmed: only y[0] (which feeds the normalization and is amplified
// by up to ~1/y0 on outlier threads) carries DS accuracy; all tapped outputs
// y[1..31], the norm*z^l chain, sin(x) and the divisions run at fp32/MUFU
// accuracy (~2e-5 per-element, pure relative factors, 30x under threshold).
//
// Thread = one (n,k). Warp = one n, k=0..31 -> coalesced 128B stores per l.

#define NPTS   65536
#define KMAX   32
#define LMAX   32
#define LSTART 49   // L_MAX + int(sqrt(10*L_MAX)) = 32 + 17

// a + b and a - b as FFMA with immediate +-1.0 multiplier.
__device__ __forceinline__ float fa(float a, float b) {
    float d; asm("fma.rn.f32 %0,%1,0f3F800000,%2;" : "=f"(d) : "f"(a), "f"(b)); return d;
}
__device__ __forceinline__ float fs(float a, float b) {  // a - b
    float d; asm("fma.rn.f32 %0,%1,0fBF800000,%2;" : "=f"(d) : "f"(b), "f"(a)); return d;
}

__global__ void __launch_bounds__(256)
sph_bessel_p(const float* __restrict__ r, float* __restrict__ out) {
    int tid = blockIdx.x * 256 + threadIdx.x;
    int n  = tid >> 5;
    int kk = tid & 31;                    // k = kk+1
    float kf = (float)(kk + 1);
    float rv = __ldg(&r[n]);

    // exact DS x = r*k
    float xh = rv * kf;
    float xl = fmaf(rv, kf, -xh);

    // sigma = 0.25 / 2^floor(log2 max(x,99)) via exponent arithmetic (exact pow2)
    float m = fmaxf(xh, 99.0f);
    int pb = __float_as_int(m) & 0x7f800000;
    float sigma = __int_as_float(0x7E000000 - pb);   // (252 - e_biased)<<23

    // z = x*sigma (exact), X2 = z^2 as DS
    float zh = xh * sigma, zl = xl * sigma;
    float X2h = zh * zh;
    float X2l = fmaf(zh, zh, -X2h);
    X2l = fmaf(zh, 2.0f * zl, X2l);
    X2l = fmaf(zl, zl, X2l);

    // state: A = S_l, B = S_{l+1}, unnormalized DS pairs. Init (2^70, 0).
    float Ah = 0x1p70f, Al = 0.0f, Bh = 0.0f, Bl = 0.0f;
    float y[LMAX];
    float y0 = 0.0f;

    #pragma unroll
    for (int i = LSTART; i >= 1; --i) {
        float cs = (float)(2 * i + 1) * sigma;   // exact (c<=99 int * pow2)

        // t = cs (x) A   (DS product, exact residual)
        float th = cs * Ah;
        float te = fmaf(cs, Ah, -th);
        te = fmaf(cs, Al, te);

        // u = X2 (x) B
        float uh = X2h * Bh;
        float ue = fmaf(X2h, Bh, -uh);
        ue = fmaf(X2h, Bl, ue);
        ue = fmaf(X2l, Bh, ue);

        // C = t - u : branchless Knuth two-sum of (th, -uh)
        float sh = fs(th, uh);
        float v  = fs(sh, th);
        float w  = fs(sh, v);
        float e1 = fs(th, w);
        float t1 = fa(uh, v);
        float er = fs(e1, t1);        // exact two-sum error
        float lo = fa(er, te);
        lo = fs(lo, ue);

        Bh = Ah; Bl = Al;             // register rename, free
        Ah = sh; Al = lo;

        if (i == 1)         y0 = fa(sh, lo);     // only y[0] needs DS rounding
        else if (i <= LMAX) y[i - 1] = sh;       // high word is enough (2^-24 rel)
    }
    y[0] = y0;

    // normalization: true j0 = sin(x)/x (MUFU), x_lo phase compensation.
    // norm = sin(x)*sqrt(2/pi)*k / (x * y0);  out[l] = y[l] * norm * z^l
    float s, cc;
    __sincosf(xh, &s, &cc);
    s = fmaf(xl, cc, s);
    float num = s * (0.7978845608028654f * kf);
    float den = xh * y0;
    float norm = __fdividef(num, den);

    float* o = out + (size_t)n * (LMAX * KMAX) + kk;
    #pragma unroll
    for (int l = 0; l < LMAX; ++l) {
        o[(size_t)l * KMAX] = y[l] * norm;   // warp-coalesced 128B per l
        norm *= zh;                           // uncompensated: <= 31 ulp total
    }
}

extern "C" void kernel_launch(void* const* d_in, const int* in_sizes, int n_in,
                              void* d_out, int out_size) {
    const float* r = (const float*)d_in[0];
    float* out = (float*)d_out;
    int total = NPTS * KMAX;                  // 2,097,152 threads
    sph_bessel_p<<<total / 256, 256>>>(r, out);
}